// round 5
// baseline (speedup 1.0000x reference)
#include <cuda_runtime.h>
#include <cuda_bf16.h>
#include <cstdint>

// Problem constants
#define T_STEPS 365
#define HID     64
#define NCELL   (256 * 256)
#define THREADS 512
#define BLOCKS  (NCELL / THREADS)   // 128

// Shared memory layout (floats)
#define SM_W    0          // W_hh: 192*64 = 12288 floats (row-major [j][k])
#define SM_H    12288      // h_next staging: 32 pairs * 1024 = 32768 floats
#define SM_WIH  45056      // W_ih: 192*2 = 384
#define SM_B    45440      // bias: 192
#define SM_BN   45632      // bias_n: 64
#define SM_OW   45696      // out_w: 64
#define SM_H0   45760      // init_h: 64
#define SM_OB   45824      // out_b: 1
#define SM_FLOATS 45828
#define SMEM_BYTES (SM_FLOATS * 4)

// Packed f32x2 FMA (Blackwell packed fp32 path; ptxas will not auto-fuse)
#define FMA2(d, a, b, c) \
    asm("fma.rn.f32x2 %0, %1, %2, %3;" : "=l"(d) : "l"(a), "l"(b), "l"(c))

__device__ __forceinline__ unsigned long long pack2(float lo, float hi) {
    unsigned long long r;
    asm("mov.b64 %0, {%1, %2};" : "=l"(r) : "f"(lo), "f"(hi));
    return r;
}

__device__ __forceinline__ float2 unpack2(unsigned long long p) {
    float lo, hi;
    asm("mov.b64 {%0, %1}, %2;" : "=f"(lo), "=f"(hi) : "l"(p));
    return make_float2(lo, hi);
}

__device__ __forceinline__ float fast_sigmoid(float x) {
    // 1/(1+e^-x): EX2 + RCP.  Saturates correctly at +-inf (1/inf = 0).
    return __fdividef(1.0f, 1.0f + __expf(-x));
}

__device__ __forceinline__ float fast_tanh(float x) {
    // tanh via e^(-2|x|) in (0,1]: no overflow/NaN for large |x|.
    float t = __expf(-2.0f * fabsf(x));
    float r = __fdividef(1.0f - t, 1.0f + t);
    return copysignf(r, x);
}

__global__ __launch_bounds__(THREADS, 1)
void gru_grid_kernel(const float* __restrict__ precip,
                     const float* __restrict__ temp,
                     const float* __restrict__ w_ih,
                     const float* __restrict__ w_hh,
                     const float* __restrict__ bias,
                     const float* __restrict__ bias_n,
                     const float* __restrict__ out_w,
                     const float* __restrict__ out_b,
                     const float* __restrict__ init_h,
                     float* __restrict__ out,
                     int write_final)
{
    extern __shared__ __align__(16) float sm[];
    float* sW   = sm + SM_W;
    float* sH   = sm + SM_H;
    float* sWih = sm + SM_WIH;
    float* sB   = sm + SM_B;
    float* sBn  = sm + SM_BN;
    float* sOw  = sm + SM_OW;
    float* sH0  = sm + SM_H0;
    float* sOb  = sm + SM_OB;

    const int tid = threadIdx.x;

    // Cooperative weight load
    for (int i = tid; i < 192 * 64; i += THREADS) sW[i]   = w_hh[i];
    for (int i = tid; i < 384;      i += THREADS) sWih[i] = w_ih[i];
    for (int i = tid; i < 192;      i += THREADS) sB[i]   = bias[i];
    if (tid < 64) {
        sBn[tid] = bias_n[tid];
        sOw[tid] = out_w[tid];
        sH0[tid] = init_h[tid];
    }
    if (tid == 0) sOb[0] = out_b[0];
    __syncthreads();

    const int cell = blockIdx.x * THREADS + tid;
    const float out_bias = sOb[0];

    // Hidden state, packed 2 x fp32 per b64 register: hp[i] = (h[2i], h[2i+1])
    unsigned long long hp[32];
#pragma unroll
    for (int i = 0; i < 32; i++) hp[i] = pack2(sH0[2 * i], sH0[2 * i + 1]);

    for (int t = 0; t < T_STEPS; t++) {
        const float xp = precip[(size_t)t * NCELL + cell];
        const float xt = temp[(size_t)t * NCELL + cell];
        float y = out_bias;

#pragma unroll 2
        for (int j = 0; j < HID; j++) {
            const ulonglong2* __restrict__ rowR =
                (const ulonglong2*)(sW + j * 64);
            const ulonglong2* __restrict__ rowZ =
                (const ulonglong2*)(sW + (64 + j) * 64);
            const ulonglong2* __restrict__ rowN =
                (const ulonglong2*)(sW + (128 + j) * 64);

            unsigned long long ar = 0ULL, az = 0ULL, an = 0ULL;
#pragma unroll
            for (int kk = 0; kk < 16; kk++) {
                ulonglong2 wr = rowR[kk];
                ulonglong2 wz = rowZ[kk];
                ulonglong2 wn = rowN[kk];
                unsigned long long h0 = hp[2 * kk];
                unsigned long long h1 = hp[2 * kk + 1];
                FMA2(ar, wr.x, h0, ar);
                FMA2(az, wz.x, h0, az);
                FMA2(an, wn.x, h0, an);
                FMA2(ar, wr.y, h1, ar);
                FMA2(az, wz.y, h1, az);
                FMA2(an, wn.y, h1, an);
            }
            float2 arf = unpack2(ar);
            float2 azf = unpack2(az);
            float2 anf = unpack2(an);
            float hg_r = arf.x + arf.y;
            float hg_z = azf.x + azf.y;
            float hg_n = anf.x + anf.y;

            float2 wr2 = ((const float2*)sWih)[j];
            float2 wz2 = ((const float2*)sWih)[64 + j];
            float2 wn2 = ((const float2*)sWih)[128 + j];
            float ig_r = fmaf(xp, wr2.x, fmaf(xt, wr2.y, sB[j]));
            float ig_z = fmaf(xp, wz2.x, fmaf(xt, wz2.y, sB[64 + j]));
            float ig_n = fmaf(xp, wn2.x, fmaf(xt, wn2.y, sB[128 + j]));

            float r  = fast_sigmoid(ig_r + hg_r);
            float z  = fast_sigmoid(ig_z + hg_z);
            float nt = fast_tanh(fmaf(r, hg_n + sBn[j], ig_n));

            float2 hcur2 = unpack2(hp[j >> 1]);
            float hj = (j & 1) ? hcur2.y : hcur2.x;
            float hn = fmaf(z, hj - nt, nt);   // new + z*(h - new)

            y = fmaf(hn, sOw[j], y);
            // Stage h_next: pair-major layout so reload is a single LDS.64
            sH[(j >> 1) * (2 * THREADS) + 2 * tid + (j & 1)] = hn;
        }

        out[(size_t)t * NCELL + cell] = y;

        // Reload h_next into packed registers (same-thread RAW, no sync needed)
#pragma unroll
        for (int i = 0; i < 32; i++)
            hp[i] = *(const unsigned long long*)&sH[i * (2 * THREADS) + 2 * tid];
    }

    if (write_final) {
        unsigned long long* dst = (unsigned long long*)
            (out + (size_t)T_STEPS * NCELL + (size_t)cell * HID);
#pragma unroll
        for (int i = 0; i < 32; i++) dst[i] = hp[i];
    }
}

extern "C" void kernel_launch(void* const* d_in, const int* in_sizes, int n_in,
                              void* d_out, int out_size) {
    const float* precip = (const float*)d_in[0];
    const float* temp_  = (const float*)d_in[1];
    const float* w_ih   = (const float*)d_in[2];
    const float* w_hh   = (const float*)d_in[3];
    const float* bias   = (const float*)d_in[4];
    const float* bias_n = (const float*)d_in[5];
    const float* out_w  = (const float*)d_in[6];
    const float* out_b  = (const float*)d_in[7];
    const float* init_h = (const float*)d_in[8];
    float* out = (float*)d_out;

    // Only write final_h if the harness allotted space for it (smb first,
    // final_h second, matching the reference tuple order).
    int write_final =
        (out_size >= T_STEPS * NCELL + NCELL * HID) ? 1 : 0;

    cudaFuncSetAttribute(gru_grid_kernel,
                         cudaFuncAttributeMaxDynamicSharedMemorySize,
                         SMEM_BYTES);

    gru_grid_kernel<<<BLOCKS, THREADS, SMEM_BYTES>>>(
        precip, temp_, w_ih, w_hh, bias, bias_n, out_w, out_b, init_h,
        out, write_final);
}

// round 11
// speedup vs baseline: 2.0897x; 2.0897x over previous
#include <cuda_runtime.h>
#include <cuda_bf16.h>
#include <cstdint>

// ---------------- problem constants ----------------
#define T_STEPS 365
#define HID     64
#define NCELL   65536
#define NTHR    256                    // threads per CTA
#define CPT     2                      // cells per thread
#define CELLS_PER_CTA (NTHR * CPT)     // 512
#define NBLK    (NCELL / CELLS_PER_CTA) // 128 CTAs -> 1 per SM

// ---------------- SMEM layout (float offsets) ----------------
#define SM_W    0                        // W_hh: 192*64 = 12288 floats
#define SM_HA   12288                    // cell-A staging: 32 pairs * NTHR * 2 floats
#define SM_HB   (SM_HA + 32 * NTHR * 2)  // 12288 + 16384 = 28672
#define SM_C    (SM_HB + 32 * NTHR * 2)  // 45056: 64 j * 12 floats
#define SM_FLOATS (SM_C + 768)           // 45824
#define SMEM_BYTES (SM_FLOATS * 4)       // 183296 B

// Packed f32x2 FMA (proven in the 33ms kernel)
#define FMA2(d, a, b, c) \
    asm("fma.rn.f32x2 %0, %1, %2, %3;" : "=l"(d) : "l"(a), "l"(b), "l"(c))

__device__ __forceinline__ unsigned long long pack2(float lo, float hi) {
    unsigned long long r;
    asm("mov.b64 %0, {%1, %2};" : "=l"(r) : "f"(lo), "f"(hi));
    return r;
}
__device__ __forceinline__ float2 unpack2(unsigned long long p) {
    float lo, hi;
    asm("mov.b64 {%0, %1}, %2;" : "=f"(lo), "=f"(hi) : "l"(p));
    return make_float2(lo, hi);
}

__device__ __forceinline__ float fast_sigmoid(float x) {
    return __fdividef(1.0f, 1.0f + __expf(-x));
}
__device__ __forceinline__ float fast_tanh(float x) {
    float t = __expf(-2.0f * fabsf(x));
    float r = __fdividef(1.0f - t, 1.0f + t);
    return copysignf(r, x);
}

__global__ __launch_bounds__(NTHR, 1)
void gru_grid_kernel(const float* __restrict__ precip,
                     const float* __restrict__ temp_,
                     const float* __restrict__ w_ih,
                     const float* __restrict__ w_hh,
                     const float* __restrict__ bias,
                     const float* __restrict__ bias_n,
                     const float* __restrict__ out_w,
                     const float* __restrict__ out_b,
                     const float* __restrict__ init_h,
                     float* __restrict__ out,
                     int write_final)
{
    extern __shared__ __align__(16) float sm[];
    float* sW = sm + SM_W;
    float* sHA = sm + SM_HA;
    float* sHB = sm + SM_HB;
    float* sC = sm + SM_C;

    const int tid = threadIdx.x;

    // ---- cooperative weight / constant load ----
    for (int i = tid; i < 192 * 64; i += NTHR) sW[i] = w_hh[i];
    // per-gate constants: c0=(wr0,wr1,wz0,wz1)  c1=(wn0,wn1,br,bz)  c2=(bn_in,bnn,ow,0)
    for (int j = tid; j < HID; j += NTHR) {
        float* c = sC + j * 12;
        c[0] = w_ih[j * 2];          c[1] = w_ih[j * 2 + 1];
        c[2] = w_ih[(64 + j) * 2];   c[3] = w_ih[(64 + j) * 2 + 1];
        c[4] = w_ih[(128 + j) * 2];  c[5] = w_ih[(128 + j) * 2 + 1];
        c[6] = bias[j];              c[7] = bias[64 + j];
        c[8] = bias[128 + j];        c[9] = bias_n[j];
        c[10] = out_w[j];            c[11] = 0.0f;
    }
    __syncthreads();

    const int cell0 = blockIdx.x * CELLS_PER_CTA + tid;        // cell A
    const int cell1 = cell0 + NTHR;                             // cell B
    const float ob = out_b[0];

    // Hidden states, k-packed: hpX[i] = (h[2i], h[2i+1]) for cell X
    unsigned long long hpA[32], hpB[32];
#pragma unroll
    for (int i = 0; i < 32; i++) {
        unsigned long long v = pack2(init_h[2 * i], init_h[2 * i + 1]);
        hpA[i] = v;
        hpB[i] = v;
    }

    // input prefetch for t = 0
    float xpA = precip[cell0], xtA = temp_[cell0];
    float xpB = precip[cell1], xtB = temp_[cell1];

    for (int t = 0; t < T_STEPS; t++) {
        // prefetch next step's inputs (hidden under this step's math)
        const int tn = (t + 1 < T_STEPS) ? (t + 1) : t;
        const float nxpA = precip[(size_t)tn * NCELL + cell0];
        const float nxtA = temp_[(size_t)tn * NCELL + cell0];
        const float nxpB = precip[(size_t)tn * NCELL + cell1];
        const float nxtB = temp_[(size_t)tn * NCELL + cell1];

        float yA = ob, yB = ob;

#pragma unroll 2
        for (int j = 0; j < HID; j++) {
            const ulonglong2* __restrict__ rowR = (const ulonglong2*)(sW + j * 64);
            const ulonglong2* __restrict__ rowZ = (const ulonglong2*)(sW + (64 + j) * 64);
            const ulonglong2* __restrict__ rowN = (const ulonglong2*)(sW + (128 + j) * 64);

            unsigned long long arA = 0, azA = 0, anA = 0;
            unsigned long long arB = 0, azB = 0, anB = 0;
#pragma unroll
            for (int kk = 0; kk < 16; kk++) {
                ulonglong2 wr = rowR[kk];
                ulonglong2 wz = rowZ[kk];
                ulonglong2 wn = rowN[kk];
                unsigned long long a0 = hpA[2 * kk], a1 = hpA[2 * kk + 1];
                unsigned long long b0 = hpB[2 * kk], b1 = hpB[2 * kk + 1];
                FMA2(arA, wr.x, a0, arA);  FMA2(arB, wr.x, b0, arB);
                FMA2(azA, wz.x, a0, azA);  FMA2(azB, wz.x, b0, azB);
                FMA2(anA, wn.x, a0, anA);  FMA2(anB, wn.x, b0, anB);
                FMA2(arA, wr.y, a1, arA);  FMA2(arB, wr.y, b1, arB);
                FMA2(azA, wz.y, a1, azA);  FMA2(azB, wz.y, b1, azB);
                FMA2(anA, wn.y, a1, anA);  FMA2(anB, wn.y, b1, anB);
            }
            float2 u;
            u = unpack2(arA); float hrA = u.x + u.y;
            u = unpack2(azA); float hzA = u.x + u.y;
            u = unpack2(anA); float hnA = u.x + u.y;
            u = unpack2(arB); float hrB = u.x + u.y;
            u = unpack2(azB); float hzB = u.x + u.y;
            u = unpack2(anB); float hnB = u.x + u.y;

            float4 c0 = *(const float4*)(sC + j * 12);
            float4 c1 = *(const float4*)(sC + j * 12 + 4);
            float4 c2 = *(const float4*)(sC + j * 12 + 8);

            float rA = fast_sigmoid(fmaf(xpA, c0.x, fmaf(xtA, c0.y, c1.z)) + hrA);
            float zA = fast_sigmoid(fmaf(xpA, c0.z, fmaf(xtA, c0.w, c1.w)) + hzA);
            float nA = fast_tanh(fmaf(rA, hnA + c2.y,
                                      fmaf(xpA, c1.x, fmaf(xtA, c1.y, c2.x))));
            float rB = fast_sigmoid(fmaf(xpB, c0.x, fmaf(xtB, c0.y, c1.z)) + hrB);
            float zB = fast_sigmoid(fmaf(xpB, c0.z, fmaf(xtB, c0.w, c1.w)) + hzB);
            float nB = fast_tanh(fmaf(rB, hnB + c2.y,
                                      fmaf(xpB, c1.x, fmaf(xtB, c1.y, c2.x))));

            float2 ha = unpack2(hpA[j >> 1]);
            float2 hb = unpack2(hpB[j >> 1]);
            float hvA = (j & 1) ? ha.y : ha.x;
            float hvB = (j & 1) ? hb.y : hb.x;
            float hnewA = fmaf(zA, hvA - nA, nA);   // n + z*(h - n)
            float hnewB = fmaf(zB, hvB - nB, nB);

            yA = fmaf(hnewA, c2.z, yA);
            yB = fmaf(hnewB, c2.z, yB);

            // stage h_next (per-thread slot; same-thread RAW, no sync needed)
            sHA[((j >> 1) * NTHR + tid) * 2 + (j & 1)] = hnewA;
            sHB[((j >> 1) * NTHR + tid) * 2 + (j & 1)] = hnewB;
        }

        out[(size_t)t * NCELL + cell0] = yA;
        out[(size_t)t * NCELL + cell1] = yB;

        // reload packed hidden state for next step
#pragma unroll
        for (int i = 0; i < 32; i++) {
            hpA[i] = *(const unsigned long long*)&sHA[(i * NTHR + tid) * 2];
            hpB[i] = *(const unsigned long long*)&sHB[(i * NTHR + tid) * 2];
        }

        xpA = nxpA; xtA = nxtA; xpB = nxpB; xtB = nxtB;
    }

    if (write_final) {
        float* dA = out + (size_t)T_STEPS * NCELL + (size_t)cell0 * HID;
        float* dB = out + (size_t)T_STEPS * NCELL + (size_t)cell1 * HID;
#pragma unroll
        for (int i = 0; i < 32; i++) {
            float2 a = unpack2(hpA[i]);
            float2 b = unpack2(hpB[i]);
            *(float2*)(dA + 2 * i) = a;
            *(float2*)(dB + 2 * i) = b;
        }
    }
}

extern "C" void kernel_launch(void* const* d_in, const int* in_sizes, int n_in,
                              void* d_out, int out_size) {
    const float* precip = (const float*)d_in[0];
    const float* temp_  = (const float*)d_in[1];
    const float* w_ih   = (const float*)d_in[2];
    const float* w_hh   = (const float*)d_in[3];
    const float* bias   = (const float*)d_in[4];
    const float* bias_n = (const float*)d_in[5];
    const float* out_w  = (const float*)d_in[6];
    const float* out_b  = (const float*)d_in[7];
    const float* init_h = (const float*)d_in[8];
    float* out = (float*)d_out;

    int write_final = (out_size >= T_STEPS * NCELL + NCELL * HID) ? 1 : 0;

    cudaFuncSetAttribute(gru_grid_kernel,
                         cudaFuncAttributeMaxDynamicSharedMemorySize,
                         SMEM_BYTES);

    gru_grid_kernel<<<NBLK, NTHR, SMEM_BYTES>>>(
        precip, temp_, w_ih, w_hh, bias, bias_n, out_w, out_b, init_h,
        out, write_final);
}

// round 13
// speedup vs baseline: 4.7406x; 2.2686x over previous
#include <cuda_runtime.h>
#include <cuda_fp16.h>
#include <cstdint>
#include <cstring>

// ---------------- problem constants ----------------
#define T_STEPS 365
#define HID     64
#define NCELL   65536
#define NTHR    256                     // 8 warps
#define M_PER_WARP 64                   // cells per warp
#define CELLS_PER_CTA 512
#define NBLK    (NCELL / CELLS_PER_CTA) // 128 CTAs -> 1 per SM

// ---------------- SMEM layout (bytes) ----------------
// B fragments: 24 n-tiles * 4 k-tiles * 2 (hi,lo) * 32 lanes * 8B = 49152
#define SMB_B      0
#define SMB_C      49152                // per-gate consts: 64 * 12 floats = 3072
#define SMB_STAGE  52224                // 8 warps * 64 slots * 32 lanes * 8B = 131072
#define SMB_TOTAL  183296

// ---------------- helpers ----------------
__device__ __forceinline__ uint32_t h2u(__half2 v) {
    uint32_t u; memcpy(&u, &v, 4); return u;
}
__device__ __forceinline__ __half2 u2h(uint32_t u) {
    __half2 v; memcpy(&v, &u, 4); return v;
}

__device__ __forceinline__ void mma16816(float& d0, float& d1, float& d2, float& d3,
                                         uint32_t a0, uint32_t a1, uint32_t a2, uint32_t a3,
                                         uint32_t b0, uint32_t b1) {
    asm volatile(
        "mma.sync.aligned.m16n8k16.row.col.f32.f16.f16.f32 "
        "{%0,%1,%2,%3}, {%4,%5,%6,%7}, {%8,%9}, {%0,%1,%2,%3};"
        : "+f"(d0), "+f"(d1), "+f"(d2), "+f"(d3)
        : "r"(a0), "r"(a1), "r"(a2), "r"(a3), "r"(b0), "r"(b1));
}

__device__ __forceinline__ float tanh_a(float x) {
    float r; asm("tanh.approx.f32 %0, %1;" : "=f"(r) : "f"(x)); return r;
}
__device__ __forceinline__ float sigm_a(float x) {
    return fmaf(0.5f, tanh_a(0.5f * x), 0.5f);
}

// pack (v0 -> low half, v1 -> high half) as hi/lo fp16 pair -> 8 bytes
__device__ __forceinline__ unsigned long long pack_hl(float v0, float v1) {
    __half2 hi2 = __floats2half2_rn(v0, v1);
    float q0 = v0 - __low2float(hi2);
    float q1 = v1 - __high2float(hi2);
    __half2 lo2 = __floats2half2_rn(q0, q1);
    return (unsigned long long)h2u(hi2) | ((unsigned long long)h2u(lo2) << 32);
}

// ---------------- kernel ----------------
__global__ __launch_bounds__(NTHR, 1)
void gru_mma_kernel(const float* __restrict__ precip,
                    const float* __restrict__ temp_,
                    const float* __restrict__ w_ih,
                    const float* __restrict__ w_hh,
                    const float* __restrict__ bias,
                    const float* __restrict__ bias_n,
                    const float* __restrict__ out_w,
                    const float* __restrict__ out_b,
                    const float* __restrict__ init_h,
                    float* __restrict__ out,
                    int write_final)
{
    extern __shared__ __align__(16) char smem[];
    unsigned long long* sB = (unsigned long long*)(smem + SMB_B);
    float* sC = (float*)(smem + SMB_C);

    const int tid  = threadIdx.x;
    const int warp = tid >> 5;
    const int lane = tid & 31;
    const int grp  = lane >> 2;   // row group within tile (0..7)
    const int tig  = lane & 3;    // thread-in-group (0..3)

    // ---- B fragments: W_hh^T as m16n8k16 col-major B frags, fp16 hi/lo ----
    // frag (nt, kt, lane): gate g = nt*8 + lane/4; k rows = kt*16 + tig*2 +{0,1,8,9}
    for (int idx = tid; idx < 24 * 4 * 32; idx += NTHR) {
        int l  = idx & 31;
        int fr = idx >> 5;           // nt*4 + kt
        int kt = fr & 3, nt = fr >> 2;
        int g  = nt * 8 + (l >> 2);
        int k0 = kt * 16 + (l & 3) * 2;
        float w00 = w_hh[g * 64 + k0],     w01 = w_hh[g * 64 + k0 + 1];
        float w10 = w_hh[g * 64 + k0 + 8], w11 = w_hh[g * 64 + k0 + 9];
        __half a = __float2half_rn(w00), b = __float2half_rn(w01);
        __half c = __float2half_rn(w10), d = __float2half_rn(w11);
        __half2 r0 = __halves2half2(a, b), r1 = __halves2half2(c, d);
        sB[(fr * 2 + 0) * 32 + l] =
            (unsigned long long)h2u(r0) | ((unsigned long long)h2u(r1) << 32);
        __half2 l0 = __floats2half2_rn(w00 - __half2float(a), w01 - __half2float(b));
        __half2 l1 = __floats2half2_rn(w10 - __half2float(c), w11 - __half2float(d));
        sB[(fr * 2 + 1) * 32 + l] =
            (unsigned long long)h2u(l0) | ((unsigned long long)h2u(l1) << 32);
    }
    // ---- per-gate constants: c0=(wr0,wr1,wz0,wz1) c1=(wn0,wn1,br,bz) c2=(bn_in,bnn,ow,0)
    for (int j = tid; j < HID; j += NTHR) {
        float* c = sC + j * 12;
        c[0] = w_ih[j * 2];           c[1] = w_ih[j * 2 + 1];
        c[2] = w_ih[(64 + j) * 2];    c[3] = w_ih[(64 + j) * 2 + 1];
        c[4] = w_ih[(128 + j) * 2];   c[5] = w_ih[(128 + j) * 2 + 1];
        c[6] = bias[j];               c[7] = bias[64 + j];
        c[8] = bias[128 + j];         c[9] = bias_n[j];
        c[10] = out_w[j];             c[11] = 0.0f;
    }

    // ---- staging prefill with init_h (per-lane slots; value identical per cell) ----
    unsigned long long* stg =
        (unsigned long long*)(smem + SMB_STAGE + warp * 16384);
    for (int s = 0; s < 64; s++) {
        int kt = (s >> 2) & 3, r = s & 3;
        int c0 = kt * 16 + tig * 2 + ((r & 2) ? 8 : 0);
        stg[s * 32 + lane] = pack_hl(init_h[c0], init_h[c0 + 1]);
    }
    __syncthreads();

    const int cellBase = blockIdx.x * CELLS_PER_CTA + warp * M_PER_WARP;
    const float ob = out_b[0];

    uint32_t Ah[4][4][4], Al[4][4][4];

    for (int t = 0; t < T_STEPS; t++) {
        // ---- load A fragments (current h, fp16 hi/lo) from staging ----
#pragma unroll
        for (int m = 0; m < 4; m++)
#pragma unroll
            for (int kt = 0; kt < 4; kt++)
#pragma unroll
                for (int r = 0; r < 4; r++) {
                    unsigned long long v = stg[((m * 4 + kt) * 4 + r) * 32 + lane];
                    Ah[m][kt][r] = (uint32_t)v;
                    Al[m][kt][r] = (uint32_t)(v >> 32);
                }

        // ---- inputs for this step (8 cells per lane) ----
        float xp[8], xt[8];
#pragma unroll
        for (int m = 0; m < 4; m++)
#pragma unroll
            for (int hf = 0; hf < 2; hf++) {
                int cell = cellBase + m * 16 + grp + hf * 8;
                xp[m * 2 + hf] = precip[(size_t)t * NCELL + cell];
                xt[m * 2 + hf] = temp_[(size_t)t * NCELL + cell];
            }

        float y[8];
#pragma unroll
        for (int i = 0; i < 8; i++) y[i] = 0.0f;

#pragma unroll 1
        for (int jt2 = 0; jt2 < 8; jt2++) {
            float dr[4][4], dz[4][4], dn[4][4];
#pragma unroll
            for (int m = 0; m < 4; m++)
#pragma unroll
                for (int e = 0; e < 4; e++) { dr[m][e] = 0.f; dz[m][e] = 0.f; dn[m][e] = 0.f; }

#pragma unroll
            for (int kt = 0; kt < 4; kt++) {
                int frR = ((jt2)      * 4 + kt) * 2;
                int frZ = ((8 + jt2)  * 4 + kt) * 2;
                int frN = ((16 + jt2) * 4 + kt) * 2;
                unsigned long long bhr = sB[(frR)     * 32 + lane];
                unsigned long long blr = sB[(frR + 1) * 32 + lane];
                unsigned long long bhz = sB[(frZ)     * 32 + lane];
                unsigned long long blz = sB[(frZ + 1) * 32 + lane];
                unsigned long long bhn = sB[(frN)     * 32 + lane];
                unsigned long long bln = sB[(frN + 1) * 32 + lane];
                uint32_t bhr0 = (uint32_t)bhr, bhr1 = (uint32_t)(bhr >> 32);
                uint32_t blr0 = (uint32_t)blr, blr1 = (uint32_t)(blr >> 32);
                uint32_t bhz0 = (uint32_t)bhz, bhz1 = (uint32_t)(bhz >> 32);
                uint32_t blz0 = (uint32_t)blz, blz1 = (uint32_t)(blz >> 32);
                uint32_t bhn0 = (uint32_t)bhn, bhn1 = (uint32_t)(bhn >> 32);
                uint32_t bln0 = (uint32_t)bln, bln1 = (uint32_t)(bln >> 32);
#pragma unroll
                for (int m = 0; m < 4; m++) {
                    uint32_t a0 = Ah[m][kt][0], a1 = Ah[m][kt][1],
                             a2 = Ah[m][kt][2], a3 = Ah[m][kt][3];
                    uint32_t l0 = Al[m][kt][0], l1 = Al[m][kt][1],
                             l2 = Al[m][kt][2], l3 = Al[m][kt][3];
                    mma16816(dr[m][0], dr[m][1], dr[m][2], dr[m][3], a0,a1,a2,a3, bhr0,bhr1);
                    mma16816(dr[m][0], dr[m][1], dr[m][2], dr[m][3], l0,l1,l2,l3, bhr0,bhr1);
                    mma16816(dr[m][0], dr[m][1], dr[m][2], dr[m][3], a0,a1,a2,a3, blr0,blr1);
                    mma16816(dz[m][0], dz[m][1], dz[m][2], dz[m][3], a0,a1,a2,a3, bhz0,bhz1);
                    mma16816(dz[m][0], dz[m][1], dz[m][2], dz[m][3], l0,l1,l2,l3, bhz0,bhz1);
                    mma16816(dz[m][0], dz[m][1], dz[m][2], dz[m][3], a0,a1,a2,a3, blz0,blz1);
                    mma16816(dn[m][0], dn[m][1], dn[m][2], dn[m][3], a0,a1,a2,a3, bhn0,bhn1);
                    mma16816(dn[m][0], dn[m][1], dn[m][2], dn[m][3], l0,l1,l2,l3, bhn0,bhn1);
                    mma16816(dn[m][0], dn[m][1], dn[m][2], dn[m][3], a0,a1,a2,a3, bln0,bln1);
                }
            }

            // ---- epilogue: gates g0 = jt2*8 + 2*tig, g1 = g0+1 ----
            int g0 = jt2 * 8 + tig * 2;
            float4 cA0 = *(const float4*)(sC + g0 * 12);
            float4 cA1 = *(const float4*)(sC + g0 * 12 + 4);
            float4 cA2 = *(const float4*)(sC + g0 * 12 + 8);
            float4 cB0 = *(const float4*)(sC + (g0 + 1) * 12);
            float4 cB1 = *(const float4*)(sC + (g0 + 1) * 12 + 4);
            float4 cB2 = *(const float4*)(sC + (g0 + 1) * 12 + 8);

            int ktj  = jt2 >> 1;
            int rsel = (jt2 & 1) * 2;

#pragma unroll
            for (int m = 0; m < 4; m++)
#pragma unroll
                for (int hf = 0; hf < 2; hf++) {
                    int s = (m * 4 + ktj) * 4 + rsel + hf;
                    unsigned long long ov = stg[s * 32 + lane];
                    __half2 ohi = u2h((uint32_t)ov), olo = u2h((uint32_t)(ov >> 32));
                    float ho0 = __low2float(ohi)  + __low2float(olo);
                    float ho1 = __high2float(ohi) + __high2float(olo);

                    float xpp = xp[m * 2 + hf], xtt = xt[m * 2 + hf];
                    float r0 = sigm_a(dr[m][hf * 2]     + fmaf(xpp, cA0.x, fmaf(xtt, cA0.y, cA1.z)));
                    float z0 = sigm_a(dz[m][hf * 2]     + fmaf(xpp, cA0.z, fmaf(xtt, cA0.w, cA1.w)));
                    float n0 = tanh_a(fmaf(r0, dn[m][hf * 2] + cA2.y,
                                           fmaf(xpp, cA1.x, fmaf(xtt, cA1.y, cA2.x))));
                    float h0 = fmaf(z0, ho0 - n0, n0);

                    float r1 = sigm_a(dr[m][hf * 2 + 1] + fmaf(xpp, cB0.x, fmaf(xtt, cB0.y, cB1.z)));
                    float z1 = sigm_a(dz[m][hf * 2 + 1] + fmaf(xpp, cB0.z, fmaf(xtt, cB0.w, cB1.w)));
                    float n1 = tanh_a(fmaf(r1, dn[m][hf * 2 + 1] + cB2.y,
                                           fmaf(xpp, cB1.x, fmaf(xtt, cB1.y, cB2.x))));
                    float h1 = fmaf(z1, ho1 - n1, n1);

                    y[m * 2 + hf] = fmaf(h0, cA2.z, fmaf(h1, cB2.z, y[m * 2 + hf]));

                    stg[s * 32 + lane] = pack_hl(h0, h1);
                }
        }

        // ---- y reduction over the 4 lanes of each row group, then store ----
#pragma unroll
        for (int i = 0; i < 8; i++) {
            y[i] += __shfl_xor_sync(0xffffffffu, y[i], 1);
            y[i] += __shfl_xor_sync(0xffffffffu, y[i], 2);
        }
        if (tig == 0) {
#pragma unroll
            for (int m = 0; m < 4; m++)
#pragma unroll
                for (int hf = 0; hf < 2; hf++)
                    out[(size_t)t * NCELL + cellBase + m * 16 + grp + hf * 8] =
                        y[m * 2 + hf] + ob;
        }
    }

    // ---- final hidden state from staging ----
    if (write_final) {
        float* base = out + (size_t)T_STEPS * NCELL;
#pragma unroll 1
        for (int s = 0; s < 64; s++) {
            unsigned long long v = stg[s * 32 + lane];
            __half2 hi = u2h((uint32_t)v), lo = u2h((uint32_t)(v >> 32));
            float h0 = __low2float(hi)  + __low2float(lo);
            float h1 = __high2float(hi) + __high2float(lo);
            int m = s >> 4, kt = (s >> 2) & 3, r = s & 3;
            int row = grp + (r & 1) * 8;
            int col = kt * 16 + tig * 2 + ((r & 2) ? 8 : 0);
            int cell = cellBase + m * 16 + row;
            float* p = base + (size_t)cell * 64 + col;
            p[0] = h0; p[1] = h1;
        }
    }
}

extern "C" void kernel_launch(void* const* d_in, const int* in_sizes, int n_in,
                              void* d_out, int out_size) {
    const float* precip = (const float*)d_in[0];
    const float* temp_  = (const float*)d_in[1];
    const float* w_ih   = (const float*)d_in[2];
    const float* w_hh   = (const float*)d_in[3];
    const float* bias   = (const float*)d_in[4];
    const float* bias_n = (const float*)d_in[5];
    const float* out_w  = (const float*)d_in[6];
    const float* out_b  = (const float*)d_in[7];
    const float* init_h = (const float*)d_in[8];
    float* out = (float*)d_out;

    int write_final = (out_size >= T_STEPS * NCELL + NCELL * HID) ? 1 : 0;

    cudaFuncSetAttribute(gru_mma_kernel,
                         cudaFuncAttributeMaxDynamicSharedMemorySize, SMB_TOTAL);

    gru_mma_kernel<<<NBLK, NTHR, SMB_TOTAL>>>(
        precip, temp_, w_ih, w_hh, bias, bias_n, out_w, out_b, init_h,
        out, write_final);
}

// round 14
// speedup vs baseline: 5.7817x; 1.2196x over previous
#include <cuda_runtime.h>
#include <cuda_fp16.h>
#include <cstdint>
#include <cstring>

// ---------------- problem constants ----------------
#define T_STEPS 365
#define HID     64
#define NCELL   65536
#define NTHR    512                     // 16 warps
#define M_PER_WARP 32                   // cells per warp (2 m16 tiles)
#define CELLS_PER_CTA 512
#define NBLK    (NCELL / CELLS_PER_CTA) // 128 CTAs -> 1 per SM

// ---------------- SMEM layout (bytes) ----------------
// B hi frags: 24 n-tiles * 4 k-tiles * 32 lanes * 8B = 24576
// B lo frags (n-gate only): 8 * 4 * 32 * 8B        =  8192
#define SMB_BHI    0
#define SMB_BLO    24576
#define SMB_C      32768                // 64 gates * 12 floats = 3072
#define SMB_STAGE  35840                // 16 warps * 32 slots * 32 lanes * 8B = 131072
#define SMB_TOTAL  166912

// ---------------- helpers ----------------
__device__ __forceinline__ uint32_t h2u(__half2 v) {
    uint32_t u; memcpy(&u, &v, 4); return u;
}
__device__ __forceinline__ __half2 u2h(uint32_t u) {
    __half2 v; memcpy(&v, &u, 4); return v;
}

__device__ __forceinline__ void mma16816(float& d0, float& d1, float& d2, float& d3,
                                         uint32_t a0, uint32_t a1, uint32_t a2, uint32_t a3,
                                         uint32_t b0, uint32_t b1) {
    asm volatile(
        "mma.sync.aligned.m16n8k16.row.col.f32.f16.f16.f32 "
        "{%0,%1,%2,%3}, {%4,%5,%6,%7}, {%8,%9}, {%0,%1,%2,%3};"
        : "+f"(d0), "+f"(d1), "+f"(d2), "+f"(d3)
        : "r"(a0), "r"(a1), "r"(a2), "r"(a3), "r"(b0), "r"(b1));
}

__device__ __forceinline__ float tanh_a(float x) {
    float r; asm("tanh.approx.f32 %0, %1;" : "=f"(r) : "f"(x)); return r;
}
__device__ __forceinline__ float sigm_a(float x) {
    return fmaf(0.5f, tanh_a(0.5f * x), 0.5f);
}

// pack (v0 -> low half, v1 -> high half) as hi/lo fp16 pair -> 8 bytes
__device__ __forceinline__ unsigned long long pack_hl(float v0, float v1) {
    __half2 hi2 = __floats2half2_rn(v0, v1);
    float q0 = v0 - __low2float(hi2);
    float q1 = v1 - __high2float(hi2);
    __half2 lo2 = __floats2half2_rn(q0, q1);
    return (unsigned long long)h2u(hi2) | ((unsigned long long)h2u(lo2) << 32);
}

// ---------------- kernel ----------------
__global__ __launch_bounds__(NTHR, 1)
void gru_mma_kernel(const float* __restrict__ precip,
                    const float* __restrict__ temp_,
                    const float* __restrict__ w_ih,
                    const float* __restrict__ w_hh,
                    const float* __restrict__ bias,
                    const float* __restrict__ bias_n,
                    const float* __restrict__ out_w,
                    const float* __restrict__ out_b,
                    const float* __restrict__ init_h,
                    float* __restrict__ out,
                    int write_final)
{
    extern __shared__ __align__(16) char smem[];
    unsigned long long* sBh = (unsigned long long*)(smem + SMB_BHI);
    unsigned long long* sBl = (unsigned long long*)(smem + SMB_BLO);
    float* sC = (float*)(smem + SMB_C);

    const int tid  = threadIdx.x;
    const int warp = tid >> 5;
    const int lane = tid & 31;
    const int grp  = lane >> 2;   // row group within tile (0..7)
    const int tig  = lane & 3;    // thread-in-group (0..3)

    // ---- B hi fragments: W_hh^T as m16n8k16 col-major B frags ----
    for (int idx = tid; idx < 96 * 32; idx += NTHR) {
        int l  = idx & 31;
        int fr = idx >> 5;           // nt*4 + kt
        int kt = fr & 3, nt = fr >> 2;
        int g  = nt * 8 + (l >> 2);
        int k0 = kt * 16 + (l & 3) * 2;
        float w00 = w_hh[g * 64 + k0],     w01 = w_hh[g * 64 + k0 + 1];
        float w10 = w_hh[g * 64 + k0 + 8], w11 = w_hh[g * 64 + k0 + 9];
        __half2 r0 = __floats2half2_rn(w00, w01);
        __half2 r1 = __floats2half2_rn(w10, w11);
        sBh[fr * 32 + l] =
            (unsigned long long)h2u(r0) | ((unsigned long long)h2u(r1) << 32);
    }
    // ---- B lo fragments for the n-gate tiles (nt 16..23) ----
    for (int idx = tid; idx < 32 * 32; idx += NTHR) {
        int l  = idx & 31;
        int fr = idx >> 5;           // (nt-16)*4 + kt
        int kt = fr & 3, nt = 16 + (fr >> 2);
        int g  = nt * 8 + (l >> 2);
        int k0 = kt * 16 + (l & 3) * 2;
        float w00 = w_hh[g * 64 + k0],     w01 = w_hh[g * 64 + k0 + 1];
        float w10 = w_hh[g * 64 + k0 + 8], w11 = w_hh[g * 64 + k0 + 9];
        __half2 r0 = __floats2half2_rn(w00, w01);
        __half2 r1 = __floats2half2_rn(w10, w11);
        __half2 l0 = __floats2half2_rn(w00 - __low2float(r0), w01 - __high2float(r0));
        __half2 l1 = __floats2half2_rn(w10 - __low2float(r1), w11 - __high2float(r1));
        sBl[fr * 32 + l] =
            (unsigned long long)h2u(l0) | ((unsigned long long)h2u(l1) << 32);
    }
    // ---- per-gate constants: c0=(wr0,wr1,wz0,wz1) c1=(wn0,wn1,br,bz) c2=(bn_in,bnn,ow,0)
    for (int j = tid; j < HID; j += NTHR) {
        float* c = sC + j * 12;
        c[0] = w_ih[j * 2];           c[1] = w_ih[j * 2 + 1];
        c[2] = w_ih[(64 + j) * 2];    c[3] = w_ih[(64 + j) * 2 + 1];
        c[4] = w_ih[(128 + j) * 2];   c[5] = w_ih[(128 + j) * 2 + 1];
        c[6] = bias[j];               c[7] = bias[64 + j];
        c[8] = bias[128 + j];         c[9] = bias_n[j];
        c[10] = out_w[j];             c[11] = 0.0f;
    }

    // ---- staging prefill with init_h (lane-private slots) ----
    unsigned long long* stg =
        (unsigned long long*)(smem + SMB_STAGE + warp * 8192);
    for (int s = 0; s < 32; s++) {
        int kt = (s >> 2) & 3, r = s & 3;
        int c0 = kt * 16 + tig * 2 + ((r & 2) ? 8 : 0);
        stg[s * 32 + lane] = pack_hl(init_h[c0], init_h[c0 + 1]);
    }
    __syncthreads();

    const int cellBase = blockIdx.x * CELLS_PER_CTA + warp * M_PER_WARP;
    const float ob = out_b[0];

    uint32_t Ah[2][4][4], Al[2][4][4];

    for (int t = 0; t < T_STEPS; t++) {
        // ---- load A fragments (current h, fp16 hi/lo) from staging ----
#pragma unroll
        for (int m = 0; m < 2; m++)
#pragma unroll
            for (int kt = 0; kt < 4; kt++)
#pragma unroll
                for (int r = 0; r < 4; r++) {
                    unsigned long long v = stg[((m * 4 + kt) * 4 + r) * 32 + lane];
                    Ah[m][kt][r] = (uint32_t)v;
                    Al[m][kt][r] = (uint32_t)(v >> 32);
                }

        // ---- inputs for this step (4 cells per lane) ----
        float xp[4], xt[4];
#pragma unroll
        for (int m = 0; m < 2; m++)
#pragma unroll
            for (int hf = 0; hf < 2; hf++) {
                int cell = cellBase + m * 16 + grp + hf * 8;
                xp[m * 2 + hf] = precip[(size_t)t * NCELL + cell];
                xt[m * 2 + hf] = temp_[(size_t)t * NCELL + cell];
            }

        float y[4] = {0.f, 0.f, 0.f, 0.f};

#pragma unroll 1
        for (int jt2 = 0; jt2 < 8; jt2++) {
            float dr[2][4], dz[2][4], dn[2][4];
#pragma unroll
            for (int m = 0; m < 2; m++)
#pragma unroll
                for (int e = 0; e < 4; e++) { dr[m][e] = 0.f; dz[m][e] = 0.f; dn[m][e] = 0.f; }

#pragma unroll
            for (int kt = 0; kt < 4; kt++) {
                unsigned long long bhr = sBh[((jt2)      * 4 + kt) * 32 + lane];
                unsigned long long bhz = sBh[((8 + jt2)  * 4 + kt) * 32 + lane];
                unsigned long long bhn = sBh[((16 + jt2) * 4 + kt) * 32 + lane];
                unsigned long long bln = sBl[((jt2)      * 4 + kt) * 32 + lane];
                uint32_t bhr0 = (uint32_t)bhr, bhr1 = (uint32_t)(bhr >> 32);
                uint32_t bhz0 = (uint32_t)bhz, bhz1 = (uint32_t)(bhz >> 32);
                uint32_t bhn0 = (uint32_t)bhn, bhn1 = (uint32_t)(bhn >> 32);
                uint32_t bln0 = (uint32_t)bln, bln1 = (uint32_t)(bln >> 32);
#pragma unroll
                for (int m = 0; m < 2; m++) {
                    uint32_t a0 = Ah[m][kt][0], a1 = Ah[m][kt][1],
                             a2 = Ah[m][kt][2], a3 = Ah[m][kt][3];
                    uint32_t l0 = Al[m][kt][0], l1 = Al[m][kt][1],
                             l2 = Al[m][kt][2], l3 = Al[m][kt][3];
                    // r,z: 2-term (Ah*Bh + Al*Bh);  n: 3-term (+ Ah*Bl)
                    mma16816(dr[m][0], dr[m][1], dr[m][2], dr[m][3], a0,a1,a2,a3, bhr0,bhr1);
                    mma16816(dr[m][0], dr[m][1], dr[m][2], dr[m][3], l0,l1,l2,l3, bhr0,bhr1);
                    mma16816(dz[m][0], dz[m][1], dz[m][2], dz[m][3], a0,a1,a2,a3, bhz0,bhz1);
                    mma16816(dz[m][0], dz[m][1], dz[m][2], dz[m][3], l0,l1,l2,l3, bhz0,bhz1);
                    mma16816(dn[m][0], dn[m][1], dn[m][2], dn[m][3], a0,a1,a2,a3, bhn0,bhn1);
                    mma16816(dn[m][0], dn[m][1], dn[m][2], dn[m][3], l0,l1,l2,l3, bhn0,bhn1);
                    mma16816(dn[m][0], dn[m][1], dn[m][2], dn[m][3], a0,a1,a2,a3, bln0,bln1);
                }
            }

            // ---- epilogue: gates g0 = jt2*8 + 2*tig, g1 = g0+1 ----
            int g0 = jt2 * 8 + tig * 2;
            float4 cA0 = *(const float4*)(sC + g0 * 12);
            float4 cA1 = *(const float4*)(sC + g0 * 12 + 4);
            float4 cA2 = *(const float4*)(sC + g0 * 12 + 8);
            float4 cB0 = *(const float4*)(sC + (g0 + 1) * 12);
            float4 cB1 = *(const float4*)(sC + (g0 + 1) * 12 + 4);
            float4 cB2 = *(const float4*)(sC + (g0 + 1) * 12 + 8);

            int ktj  = jt2 >> 1;
            int rsel = (jt2 & 1) * 2;

#pragma unroll
            for (int m = 0; m < 2; m++)
#pragma unroll
                for (int hf = 0; hf < 2; hf++) {
                    // old h at this (cell,col) position == current A fragment regs
                    __half2 ohi = u2h(Ah[m][ktj][rsel + hf]);
                    __half2 olo = u2h(Al[m][ktj][rsel + hf]);
                    float ho0 = __low2float(ohi)  + __low2float(olo);
                    float ho1 = __high2float(ohi) + __high2float(olo);

                    float xpp = xp[m * 2 + hf], xtt = xt[m * 2 + hf];
                    float r0 = sigm_a(dr[m][hf * 2]     + fmaf(xpp, cA0.x, fmaf(xtt, cA0.y, cA1.z)));
                    float z0 = sigm_a(dz[m][hf * 2]     + fmaf(xpp, cA0.z, fmaf(xtt, cA0.w, cA1.w)));
                    float n0 = tanh_a(fmaf(r0, dn[m][hf * 2] + cA2.y,
                                           fmaf(xpp, cA1.x, fmaf(xtt, cA1.y, cA2.x))));
                    float h0 = fmaf(z0, ho0 - n0, n0);

                    float r1 = sigm_a(dr[m][hf * 2 + 1] + fmaf(xpp, cB0.x, fmaf(xtt, cB0.y, cB1.z)));
                    float z1 = sigm_a(dz[m][hf * 2 + 1] + fmaf(xpp, cB0.z, fmaf(xtt, cB0.w, cB1.w)));
                    float n1 = tanh_a(fmaf(r1, dn[m][hf * 2 + 1] + cB2.y,
                                           fmaf(xpp, cB1.x, fmaf(xtt, cB1.y, cB2.x))));
                    float h1 = fmaf(z1, ho1 - n1, n1);

                    y[m * 2 + hf] = fmaf(h0, cA2.z, fmaf(h1, cB2.z, y[m * 2 + hf]));

                    stg[((m * 4 + ktj) * 4 + rsel + hf) * 32 + lane] = pack_hl(h0, h1);
                }
        }

        // ---- y reduction over the 4 lanes of each row group, then store ----
#pragma unroll
        for (int i = 0; i < 4; i++) {
            y[i] += __shfl_xor_sync(0xffffffffu, y[i], 1);
            y[i] += __shfl_xor_sync(0xffffffffu, y[i], 2);
        }
        if (tig == 0) {
#pragma unroll
            for (int m = 0; m < 2; m++)
#pragma unroll
                for (int hf = 0; hf < 2; hf++)
                    out[(size_t)t * NCELL + cellBase + m * 16 + grp + hf * 8] =
                        y[m * 2 + hf] + ob;
        }
    }

    // ---- final hidden state from staging ----
    if (write_final) {
        float* base = out + (size_t)T_STEPS * NCELL;
#pragma unroll 1
        for (int s = 0; s < 32; s++) {
            unsigned long long v = stg[s * 32 + lane];
            __half2 hi = u2h((uint32_t)v), lo = u2h((uint32_t)(v >> 32));
            float h0 = __low2float(hi)  + __low2float(lo);
            float h1 = __high2float(hi) + __high2float(lo);
            int m = s >> 4, kt = (s >> 2) & 3, r = s & 3;
            int row = grp + (r & 1) * 8;
            int col = kt * 16 + tig * 2 + ((r & 2) ? 8 : 0);
            int cell = cellBase + m * 16 + row;
            float* p = base + (size_t)cell * 64 + col;
            p[0] = h0; p[1] = h1;
        }
    }
}

extern "C" void kernel_launch(void* const* d_in, const int* in_sizes, int n_in,
                              void* d_out, int out_size) {
    const float* precip = (const float*)d_in[0];
    const float* temp_  = (const float*)d_in[1];
    const float* w_ih   = (const float*)d_in[2];
    const float* w_hh   = (const float*)d_in[3];
    const float* bias   = (const float*)d_in[4];
    const float* bias_n = (const float*)d_in[5];
    const float* out_w  = (const float*)d_in[6];
    const float* out_b  = (const float*)d_in[7];
    const float* init_h = (const float*)d_in[8];
    float* out = (float*)d_out;

    int write_final = (out_size >= T_STEPS * NCELL + NCELL * HID) ? 1 : 0;

    cudaFuncSetAttribute(gru_mma_kernel,
                         cudaFuncAttributeMaxDynamicSharedMemorySize, SMB_TOTAL);

    gru_mma_kernel<<<NBLK, NTHR, SMB_TOTAL>>>(
        precip, temp_, w_ih, w_hh, bias, bias_n, out_w, out_b, init_h,
        out, write_final);
}

// round 15
// speedup vs baseline: 10.6692x; 1.8454x over previous
#include <cuda_runtime.h>
#include <cuda_fp16.h>
#include <cstdint>
#include <cstring>

// ---------------- problem constants ----------------
#define T_STEPS 365
#define HID     64
#define NCELL   65536
#define NTHR    512                     // 16 warps
#define M_PER_WARP 32                   // cells per warp (2 m16 tiles)
#define CELLS_PER_CTA 512
#define NBLK    (NCELL / CELLS_PER_CTA) // 128 CTAs -> 1 per SM

// ---------------- SMEM layout (bytes) ----------------
// B hi frags: 24 n-tiles * 4 k-tiles * 32 lanes * 8B = 24576
// B lo frags (n-gate only): 8 * 4 * 32 * 8B        =  8192
// consts: 64 gates * 12 floats                      =  3072
// staging: 16 warps * 32 slots * 32 lanes * 4B      = 65536
#define SMB_BHI    0
#define SMB_BLO    24576
#define SMB_C      32768
#define SMB_STAGE  35840
#define SMB_TOTAL  101376

// ---------------- helpers ----------------
__device__ __forceinline__ uint32_t h2u(__half2 v) {
    uint32_t u; memcpy(&u, &v, 4); return u;
}
__device__ __forceinline__ __half2 u2h(uint32_t u) {
    __half2 v; memcpy(&v, &u, 4); return v;
}

__device__ __forceinline__ void mma16816(float& d0, float& d1, float& d2, float& d3,
                                         uint32_t a0, uint32_t a1, uint32_t a2, uint32_t a3,
                                         uint32_t b0, uint32_t b1) {
    asm volatile(
        "mma.sync.aligned.m16n8k16.row.col.f32.f16.f16.f32 "
        "{%0,%1,%2,%3}, {%4,%5,%6,%7}, {%8,%9}, {%0,%1,%2,%3};"
        : "+f"(d0), "+f"(d1), "+f"(d2), "+f"(d3)
        : "r"(a0), "r"(a1), "r"(a2), "r"(a3), "r"(b0), "r"(b1));
}

__device__ __forceinline__ float tanh_a(float x) {
    float r; asm("tanh.approx.f32 %0, %1;" : "=f"(r) : "f"(x)); return r;
}
__device__ __forceinline__ float sigm_a(float x) {
    return fmaf(0.5f, tanh_a(0.5f * x), 0.5f);
}

// ---------------- kernel ----------------
__global__ __launch_bounds__(NTHR, 1)
void gru_mma_kernel(const float* __restrict__ precip,
                    const float* __restrict__ temp_,
                    const float* __restrict__ w_ih,
                    const float* __restrict__ w_hh,
                    const float* __restrict__ bias,
                    const float* __restrict__ bias_n,
                    const float* __restrict__ out_w,
                    const float* __restrict__ out_b,
                    const float* __restrict__ init_h,
                    float* __restrict__ out,
                    int write_final)
{
    extern __shared__ __align__(16) char smem[];
    unsigned long long* sBh = (unsigned long long*)(smem + SMB_BHI);
    unsigned long long* sBl = (unsigned long long*)(smem + SMB_BLO);
    float* sC = (float*)(smem + SMB_C);

    const int tid  = threadIdx.x;
    const int warp = tid >> 5;
    const int lane = tid & 31;
    const int grp  = lane >> 2;   // row group within tile (0..7)
    const int tig  = lane & 3;    // thread-in-group (0..3)

    // ---- B hi fragments: W_hh^T as m16n8k16 col-major B frags ----
    for (int idx = tid; idx < 96 * 32; idx += NTHR) {
        int l  = idx & 31;
        int fr = idx >> 5;           // nt*4 + kt
        int kt = fr & 3, nt = fr >> 2;
        int g  = nt * 8 + (l >> 2);
        int k0 = kt * 16 + (l & 3) * 2;
        float w00 = w_hh[g * 64 + k0],     w01 = w_hh[g * 64 + k0 + 1];
        float w10 = w_hh[g * 64 + k0 + 8], w11 = w_hh[g * 64 + k0 + 9];
        __half2 r0 = __floats2half2_rn(w00, w01);
        __half2 r1 = __floats2half2_rn(w10, w11);
        sBh[fr * 32 + l] =
            (unsigned long long)h2u(r0) | ((unsigned long long)h2u(r1) << 32);
    }
    // ---- B lo fragments for the n-gate tiles (nt 16..23) ----
    for (int idx = tid; idx < 32 * 32; idx += NTHR) {
        int l  = idx & 31;
        int fr = idx >> 5;           // (nt-16)*4 + kt
        int kt = fr & 3, nt = 16 + (fr >> 2);
        int g  = nt * 8 + (l >> 2);
        int k0 = kt * 16 + (l & 3) * 2;
        float w00 = w_hh[g * 64 + k0],     w01 = w_hh[g * 64 + k0 + 1];
        float w10 = w_hh[g * 64 + k0 + 8], w11 = w_hh[g * 64 + k0 + 9];
        __half2 r0 = __floats2half2_rn(w00, w01);
        __half2 r1 = __floats2half2_rn(w10, w11);
        __half2 l0 = __floats2half2_rn(w00 - __low2float(r0), w01 - __high2float(r0));
        __half2 l1 = __floats2half2_rn(w10 - __low2float(r1), w11 - __high2float(r1));
        sBl[fr * 32 + l] =
            (unsigned long long)h2u(l0) | ((unsigned long long)h2u(l1) << 32);
    }
    // ---- per-gate constants: c0=(wr0,wr1,wz0,wz1) c1=(wn0,wn1,br,bz) c2=(bn_in,bnn,ow,0)
    for (int j = tid; j < HID; j += NTHR) {
        float* c = sC + j * 12;
        c[0] = w_ih[j * 2];           c[1] = w_ih[j * 2 + 1];
        c[2] = w_ih[(64 + j) * 2];    c[3] = w_ih[(64 + j) * 2 + 1];
        c[4] = w_ih[(128 + j) * 2];   c[5] = w_ih[(128 + j) * 2 + 1];
        c[6] = bias[j];               c[7] = bias[64 + j];
        c[8] = bias[128 + j];         c[9] = bias_n[j];
        c[10] = out_w[j];             c[11] = 0.0f;
    }

    // ---- staging prefill with init_h (lane-private fp16x2 slots) ----
    uint32_t* stg = (uint32_t*)(smem + SMB_STAGE + warp * 4096);
    for (int s = 0; s < 32; s++) {
        int kt = (s >> 2) & 3, r = s & 3;
        int c0 = kt * 16 + tig * 2 + ((r & 2) ? 8 : 0);
        stg[s * 32 + lane] = h2u(__floats2half2_rn(init_h[c0], init_h[c0 + 1]));
    }
    __syncthreads();

    const int cellBase = blockIdx.x * CELLS_PER_CTA + warp * M_PER_WARP;
    const float ob = out_b[0];
    float* finBase = out + (size_t)T_STEPS * NCELL;

    uint32_t Ah[2][4][4];

    for (int t = 0; t < T_STEPS; t++) {
        // ---- load A fragments (current h, fp16) from staging ----
#pragma unroll
        for (int m = 0; m < 2; m++)
#pragma unroll
            for (int kt = 0; kt < 4; kt++)
#pragma unroll
                for (int r = 0; r < 4; r++)
                    Ah[m][kt][r] = stg[((m * 4 + kt) * 4 + r) * 32 + lane];

        // ---- inputs for this step (4 cells per lane) ----
        float xp[4], xt[4];
#pragma unroll
        for (int m = 0; m < 2; m++)
#pragma unroll
            for (int hf = 0; hf < 2; hf++) {
                int cell = cellBase + m * 16 + grp + hf * 8;
                xp[m * 2 + hf] = precip[(size_t)t * NCELL + cell];
                xt[m * 2 + hf] = temp_[(size_t)t * NCELL + cell];
            }

        float y[4] = {0.f, 0.f, 0.f, 0.f};
        const int last = (t == T_STEPS - 1) && write_final;

#pragma unroll 1
        for (int jt2 = 0; jt2 < 8; jt2++) {
            float dr[2][4], dz[2][4], dn[2][4];
#pragma unroll
            for (int m = 0; m < 2; m++)
#pragma unroll
                for (int e = 0; e < 4; e++) { dr[m][e] = 0.f; dz[m][e] = 0.f; dn[m][e] = 0.f; }

#pragma unroll
            for (int kt = 0; kt < 4; kt++) {
                unsigned long long bhr = sBh[((jt2)      * 4 + kt) * 32 + lane];
                unsigned long long bhz = sBh[((8 + jt2)  * 4 + kt) * 32 + lane];
                unsigned long long bhn = sBh[((16 + jt2) * 4 + kt) * 32 + lane];
                unsigned long long bln = sBl[((jt2)      * 4 + kt) * 32 + lane];
                uint32_t bhr0 = (uint32_t)bhr, bhr1 = (uint32_t)(bhr >> 32);
                uint32_t bhz0 = (uint32_t)bhz, bhz1 = (uint32_t)(bhz >> 32);
                uint32_t bhn0 = (uint32_t)bhn, bhn1 = (uint32_t)(bhn >> 32);
                uint32_t bln0 = (uint32_t)bln, bln1 = (uint32_t)(bln >> 32);
#pragma unroll
                for (int m = 0; m < 2; m++) {
                    uint32_t a0 = Ah[m][kt][0], a1 = Ah[m][kt][1],
                             a2 = Ah[m][kt][2], a3 = Ah[m][kt][3];
                    // r,z: 1-term;  n: 2-term (+ B-lo compensation)
                    mma16816(dr[m][0], dr[m][1], dr[m][2], dr[m][3], a0,a1,a2,a3, bhr0,bhr1);
                    mma16816(dz[m][0], dz[m][1], dz[m][2], dz[m][3], a0,a1,a2,a3, bhz0,bhz1);
                    mma16816(dn[m][0], dn[m][1], dn[m][2], dn[m][3], a0,a1,a2,a3, bhn0,bhn1);
                    mma16816(dn[m][0], dn[m][1], dn[m][2], dn[m][3], a0,a1,a2,a3, bln0,bln1);
                }
            }

            // ---- epilogue: gates g0 = jt2*8 + 2*tig, g1 = g0+1 ----
            int g0 = jt2 * 8 + tig * 2;
            float4 cA0 = *(const float4*)(sC + g0 * 12);
            float4 cA1 = *(const float4*)(sC + g0 * 12 + 4);
            float4 cA2 = *(const float4*)(sC + g0 * 12 + 8);
            float4 cB0 = *(const float4*)(sC + (g0 + 1) * 12);
            float4 cB1 = *(const float4*)(sC + (g0 + 1) * 12 + 4);
            float4 cB2 = *(const float4*)(sC + (g0 + 1) * 12 + 8);

            int ktj  = jt2 >> 1;
            int rsel = (jt2 & 1) * 2;

#pragma unroll
            for (int m = 0; m < 2; m++)
#pragma unroll
                for (int hf = 0; hf < 2; hf++) {
                    // old h at this (cell,col) position == current A fragment regs
                    __half2 ohi = u2h(Ah[m][ktj][rsel + hf]);
                    float ho0 = __low2float(ohi);
                    float ho1 = __high2float(ohi);

                    float xpp = xp[m * 2 + hf], xtt = xt[m * 2 + hf];
                    float r0 = sigm_a(dr[m][hf * 2]     + fmaf(xpp, cA0.x, fmaf(xtt, cA0.y, cA1.z)));
                    float z0 = sigm_a(dz[m][hf * 2]     + fmaf(xpp, cA0.z, fmaf(xtt, cA0.w, cA1.w)));
                    float n0 = tanh_a(fmaf(r0, dn[m][hf * 2] + cA2.y,
                                           fmaf(xpp, cA1.x, fmaf(xtt, cA1.y, cA2.x))));
                    float h0 = fmaf(z0, ho0 - n0, n0);

                    float r1 = sigm_a(dr[m][hf * 2 + 1] + fmaf(xpp, cB0.x, fmaf(xtt, cB0.y, cB1.z)));
                    float z1 = sigm_a(dz[m][hf * 2 + 1] + fmaf(xpp, cB0.z, fmaf(xtt, cB0.w, cB1.w)));
                    float n1 = tanh_a(fmaf(r1, dn[m][hf * 2 + 1] + cB2.y,
                                           fmaf(xpp, cB1.x, fmaf(xtt, cB1.y, cB2.x))));
                    float h1 = fmaf(z1, ho1 - n1, n1);

                    y[m * 2 + hf] = fmaf(h0, cA2.z, fmaf(h1, cB2.z, y[m * 2 + hf]));

                    stg[((m * 4 + ktj) * 4 + rsel + hf) * 32 + lane] =
                        h2u(__floats2half2_rn(h0, h1));

                    if (last) {
                        int cell = cellBase + m * 16 + grp + hf * 8;
                        *(float2*)(finBase + (size_t)cell * HID + g0) =
                            make_float2(h0, h1);
                    }
                }
        }

        // ---- y reduction over the 4 lanes of each row group, then store ----
#pragma unroll
        for (int i = 0; i < 4; i++) {
            y[i] += __shfl_xor_sync(0xffffffffu, y[i], 1);
            y[i] += __shfl_xor_sync(0xffffffffu, y[i], 2);
        }
        if (tig == 0) {
#pragma unroll
            for (int m = 0; m < 2; m++)
#pragma unroll
                for (int hf = 0; hf < 2; hf++)
                    out[(size_t)t * NCELL + cellBase + m * 16 + grp + hf * 8] =
                        y[m * 2 + hf] + ob;
        }
    }
}

extern "C" void kernel_launch(void* const* d_in, const int* in_sizes, int n_in,
                              void* d_out, int out_size) {
    const float* precip = (const float*)d_in[0];
    const float* temp_  = (const float*)d_in[1];
    const float* w_ih   = (const float*)d_in[2];
    const float* w_hh   = (const float*)d_in[3];
    const float* bias   = (const float*)d_in[4];
    const float* bias_n = (const float*)d_in[5];
    const float* out_w  = (const float*)d_in[6];
    const float* out_b  = (const float*)d_in[7];
    const float* init_h = (const float*)d_in[8];
    float* out = (float*)d_out;

    int write_final = (out_size >= T_STEPS * NCELL + NCELL * HID) ? 1 : 0;

    cudaFuncSetAttribute(gru_mma_kernel,
                         cudaFuncAttributeMaxDynamicSharedMemorySize, SMB_TOTAL);

    gru_mma_kernel<<<NBLK, NTHR, SMB_TOTAL>>>(
        precip, temp_, w_ih, w_hh, bias, bias_n, out_w, out_b, init_h,
        out, write_final);
}